// round 9
// baseline (speedup 1.0000x reference)
#include <cuda_runtime.h>

// Allpass biquad, fs=16000, f0=4000, Q=0.707. w0 = pi/2 exactly ->
// normalized: b0 = a2 = c, b2 = 1, b1 = a1 ~ 6e-17 (dropped).
// Closed FIR form: y[n] = c*x[n] + (1-c^2)*S[n],
//   S[n] = sum_{m=0..5} (-c)^m x[n-2-2m]    (tail (1-c^2)c^6 ~ 2.4e-5 << 1e-3)
//
// 16 outputs per thread: window = x[n0-12 .. n0+15] = 7 contiguous float4s.
// 7 LDG.128 + 4 STG.128 per 16 samples -> 0.086 L1 wavefronts/sample
// (0.109 at 8/thread, 0.156 at 4/thread). L1TEX is the measured limiter.

#define C_C  0.17149858514250882f
#define C_OM 0.97058823630252067f   /* 1 - c^2 */

#define THREADS 256
#define LVEC    4                    // output float4s per thread
#define NLD     7                    // window float4s per thread

__global__ __launch_bounds__(THREADS)
void allpass_fir16(const float4* __restrict__ x4,
                   float4* __restrict__ y4,
                   int NC)                           // 16-sample chunks per seq
{
    const int oc = blockIdx.x * THREADS + threadIdx.x;   // chunk index
    if (oc >= NC) return;

    const int f0  = LVEC * oc;                           // first output float4
    const int idx = blockIdx.y * (NC * LVEC) + f0;       // fits int32 (7.68M)

    const float4* p = x4 + idx;

    // ---- load window: float4s f0-3 .. f0+3  (w[j] = x[n0-12+j], j=0..27)
    float w[28];
    if (f0 >= 3) {
        #pragma unroll
        for (int j = 0; j < NLD; ++j) {
            const float4 v = __ldg(p + (j - 3));
            w[4 * j + 0] = v.x; w[4 * j + 1] = v.y;
            w[4 * j + 2] = v.z; w[4 * j + 3] = v.w;
        }
    } else {
        // sequence head (one thread per sequence): zero-pad = zero init state
        #pragma unroll
        for (int j = 0; j < NLD; ++j) {
            float4 v = make_float4(0.f, 0.f, 0.f, 0.f);
            if (f0 + (j - 3) >= 0) v = __ldg(p + (j - 3));
            w[4 * j + 0] = v.x; w[4 * j + 1] = v.y;
            w[4 * j + 2] = v.z; w[4 * j + 3] = v.w;
        }
    }

    // ---- S_i = sum_{m=0..5} (-c)^m w[10+i-2m]
    // i = 0,1 by Horner; i >= 2 by S_i = w[10+i] - c*S_{i-2}
    float S[16];
    {
        float s0 = w[0], s1 = w[1];
        #pragma unroll
        for (int j = 2; j <= 10; j += 2) {
            s0 = fmaf(-C_C, s0, w[j]);
            s1 = fmaf(-C_C, s1, w[j + 1]);
        }
        S[0] = s0; S[1] = s1;
    }
    #pragma unroll
    for (int i = 2; i < 16; ++i)
        S[i] = fmaf(-C_C, S[i - 2], w[10 + i]);

    // ---- y[n0+i] = c*x[n0+i] + (1-c^2)*S_i,  x[n0+i] = w[12+i]
    #pragma unroll
    for (int q = 0; q < LVEC; ++q) {
        float4 o;
        o.x = fmaf(C_OM, S[4 * q + 0], C_C * w[12 + 4 * q + 0]);
        o.y = fmaf(C_OM, S[4 * q + 1], C_C * w[12 + 4 * q + 1]);
        o.z = fmaf(C_OM, S[4 * q + 2], C_C * w[12 + 4 * q + 2]);
        o.w = fmaf(C_OM, S[4 * q + 3], C_C * w[12 + 4 * q + 3]);
        __stcs(y4 + idx + q, o);     // streaming store: keep L2 for x
    }
}

extern "C" void kernel_launch(void* const* d_in, const int* in_sizes, int n_in,
                              void* d_out, int out_size)
{
    const float4* x = (const float4*)d_in[0];
    float4*       y = (float4*)d_out;

    const int B  = 64;                   // fixed shape [64, 1, 480000]
    const int T  = in_sizes[0] / B;
    const int NC = T >> 4;               // 30000 chunks of 16 samples

    dim3 grid((NC + THREADS - 1) / THREADS, B, 1);
    allpass_fir16<<<grid, THREADS>>>(x, y, NC);
}

// round 10
// speedup vs baseline: 1.0129x; 1.0129x over previous
#include <cuda_runtime.h>

// Allpass biquad, fs=16000, f0=4000, Q=0.707. w0 = pi/2 exactly ->
// normalized: b0 = a2 = c, b2 = 1, b1 = a1 ~ 6e-17 (dropped).
// Closed FIR form: y[n] = c*x[n] + (1-c^2)*S[n],
//   S[n] = sum_{m=0..5} (-c)^m x[n-2-2m]    (tail (1-c^2)c^6 ~ 2.4e-5 << 1e-3)
//
// 16 outputs per thread: window = x[n0-12 .. n0+15] = 7 contiguous float4s.
// 7 LDG.128 + 4 STG.128 per 16 samples -> 0.086 L1 wavefronts/sample
// (0.109 at 8/thread, 0.156 at 4/thread). L1TEX is the measured limiter.

#define C_C  0.17149858514250882f
#define C_OM 0.97058823630252067f   /* 1 - c^2 */

#define THREADS 256
#define LVEC    4                    // output float4s per thread
#define NLD     7                    // window float4s per thread

__global__ __launch_bounds__(THREADS)
void allpass_fir16(const float4* __restrict__ x4,
                   float4* __restrict__ y4,
                   int NC)                           // 16-sample chunks per seq
{
    const int oc = blockIdx.x * THREADS + threadIdx.x;   // chunk index
    if (oc >= NC) return;

    const int f0  = LVEC * oc;                           // first output float4
    const int idx = blockIdx.y * (NC * LVEC) + f0;       // fits int32 (7.68M)

    const float4* p = x4 + idx;

    // ---- load window: float4s f0-3 .. f0+3  (w[j] = x[n0-12+j], j=0..27)
    float w[28];
    if (f0 >= 3) {
        #pragma unroll
        for (int j = 0; j < NLD; ++j) {
            const float4 v = __ldg(p + (j - 3));
            w[4 * j + 0] = v.x; w[4 * j + 1] = v.y;
            w[4 * j + 2] = v.z; w[4 * j + 3] = v.w;
        }
    } else {
        // sequence head (one thread per sequence): zero-pad = zero init state
        #pragma unroll
        for (int j = 0; j < NLD; ++j) {
            float4 v = make_float4(0.f, 0.f, 0.f, 0.f);
            if (f0 + (j - 3) >= 0) v = __ldg(p + (j - 3));
            w[4 * j + 0] = v.x; w[4 * j + 1] = v.y;
            w[4 * j + 2] = v.z; w[4 * j + 3] = v.w;
        }
    }

    // ---- S_i = sum_{m=0..5} (-c)^m w[10+i-2m]
    // i = 0,1 by Horner; i >= 2 by S_i = w[10+i] - c*S_{i-2}
    float S[16];
    {
        float s0 = w[0], s1 = w[1];
        #pragma unroll
        for (int j = 2; j <= 10; j += 2) {
            s0 = fmaf(-C_C, s0, w[j]);
            s1 = fmaf(-C_C, s1, w[j + 1]);
        }
        S[0] = s0; S[1] = s1;
    }
    #pragma unroll
    for (int i = 2; i < 16; ++i)
        S[i] = fmaf(-C_C, S[i - 2], w[10 + i]);

    // ---- y[n0+i] = c*x[n0+i] + (1-c^2)*S_i,  x[n0+i] = w[12+i]
    #pragma unroll
    for (int q = 0; q < LVEC; ++q) {
        float4 o;
        o.x = fmaf(C_OM, S[4 * q + 0], C_C * w[12 + 4 * q + 0]);
        o.y = fmaf(C_OM, S[4 * q + 1], C_C * w[12 + 4 * q + 1]);
        o.z = fmaf(C_OM, S[4 * q + 2], C_C * w[12 + 4 * q + 2]);
        o.w = fmaf(C_OM, S[4 * q + 3], C_C * w[12 + 4 * q + 3]);
        __stcs(y4 + idx + q, o);     // streaming store: keep L2 for x
    }
}

extern "C" void kernel_launch(void* const* d_in, const int* in_sizes, int n_in,
                              void* d_out, int out_size)
{
    const float4* x = (const float4*)d_in[0];
    float4*       y = (float4*)d_out;

    const int B  = 64;                   // fixed shape [64, 1, 480000]
    const int T  = in_sizes[0] / B;
    const int NC = T >> 4;               // 30000 chunks of 16 samples

    dim3 grid((NC + THREADS - 1) / THREADS, B, 1);
    allpass_fir16<<<grid, THREADS>>>(x, y, NC);
}